// round 6
// baseline (speedup 1.0000x reference)
#include <cuda_runtime.h>
#include <cuda_bf16.h>

#define NTOK 8192
#define CIN 512
#define DKH 64
#define BM 32
#define BN 16
#define PCOLS 640

// Scratch for projected Q/K/V (static device memory; no runtime allocation).
__device__ float g_q[2][NTOK * DKH];   // 2 x 2 MB
__device__ float g_k[2][NTOK * DKH];   // 2 x 2 MB
__device__ float g_v[2][NTOK * CIN];   // 2 x 16 MB

// ---------------------------------------------------------------------------
// Kernel 1: fused QKV projection. C = A[16384? no: per-image 8192,512] @ B[512,640]
// where B columns [0,64)=Wq, [64,128)=Wk, [128,640)=Wv. 64x64 output tiles.
// ---------------------------------------------------------------------------
__global__ __launch_bounds__(256, 2)
void proj_kernel(const float* __restrict__ im1, const float* __restrict__ im2,
                 const float* __restrict__ Wq, const float* __restrict__ Wk,
                 const float* __restrict__ Wv) {
    const int img = blockIdx.z;
    const float* __restrict__ A = img ? im2 : im1;
    float* __restrict__ q = g_q[img];
    float* __restrict__ k = g_k[img];
    float* __restrict__ v = g_v[img];

    __shared__ float As[64][17];
    __shared__ float Bs[16][65];

    const int tid = threadIdx.x;
    const int tx = tid & 15;
    const int ty = tid >> 4;
    const int rowBase = blockIdx.x * 64;
    const int colBase = blockIdx.y * 64;

    float acc[4][4] = {};

    for (int kt = 0; kt < CIN; kt += 16) {
        {   // A tile: 64 rows x 16 k, float4 per thread
            int r  = tid >> 2;
            int kk = (tid & 3) << 2;
            float4 a4 = *(const float4*)(A + (size_t)(rowBase + r) * CIN + kt + kk);
            As[r][kk] = a4.x; As[r][kk + 1] = a4.y; As[r][kk + 2] = a4.z; As[r][kk + 3] = a4.w;
        }
        {   // B tile: 16 k x 64 cols (branch is uniform per block)
            int kk   = tid >> 4;
            int c0   = (tid & 15) << 2;
            int kidx = kt + kk;
            #pragma unroll
            for (int j = 0; j < 4; j++) {
                int c = colBase + c0 + j;
                float w;
                if (c < 64)        w = Wq[kidx * DKH + c];
                else if (c < 128)  w = Wk[kidx * DKH + (c - 64)];
                else               w = Wv[kidx * CIN + (c - 128)];
                Bs[kk][c0 + j] = w;
            }
        }
        __syncthreads();
        #pragma unroll
        for (int kk = 0; kk < 16; kk++) {
            float a[4], b[4];
            #pragma unroll
            for (int i = 0; i < 4; i++) a[i] = As[ty * 4 + i][kk];
            #pragma unroll
            for (int j = 0; j < 4; j++) b[j] = Bs[kk][tx * 4 + j];
            #pragma unroll
            for (int i = 0; i < 4; i++)
                #pragma unroll
                for (int j = 0; j < 4; j++)
                    acc[i][j] = fmaf(a[i], b[j], acc[i][j]);
        }
        __syncthreads();
    }

    #pragma unroll
    for (int i = 0; i < 4; i++) {
        int row = rowBase + ty * 4 + i;
        #pragma unroll
        for (int j = 0; j < 4; j++) {
            int c = colBase + tx * 4 + j;
            float val = acc[i][j];
            if (c < 64)        q[row * DKH + c] = val;
            else if (c < 128)  k[row * DKH + (c - 64)] = val;
            else               v[row * CIN + (c - 128)] = val;
        }
    }
}

// ---------------------------------------------------------------------------
// Kernel 2: flash attention + residual.
// side=0: im1_out = softmax(q2 @ k1^T) @ v1 + im1
// side=1: im2_out = softmax(q1 @ k2^T) @ v2 + im2
// CTA: BM=32 query rows, 256 threads. Thread (rg=tid/32, lane=tid%32) owns
// rows rg*4..rg*4+3 and columns {lane + 32*j} (j=0..15) of the [32,512] acc.
// ---------------------------------------------------------------------------
__global__ __launch_bounds__(256, 2)
void attn_kernel(const float* __restrict__ im1, const float* __restrict__ im2,
                 float* __restrict__ out_all) {
    const int side = blockIdx.y;
    const float* __restrict__ Qp    = g_q[side ? 0 : 1];  // cross: out1 uses im2_q
    const float* __restrict__ Kp    = g_k[side ? 1 : 0];
    const float* __restrict__ Vp    = g_v[side ? 1 : 0];
    const float* __restrict__ resid = side ? im2 : im1;
    float* __restrict__ out = out_all + (size_t)side * NTOK * CIN;

    __shared__ float Qs[BM][68];
    __shared__ float Ks[BN][68];
    __shared__ float Vs[BN][CIN];
    __shared__ float Ss[BM][17];
    __shared__ float m_s[BM], l_s[BM], corr_s[BM];

    const int tid   = threadIdx.x;
    const int lane  = tid & 31;
    const int rg    = tid >> 5;
    const int qBase = blockIdx.x * BM;

    // Load Q tile once (32 x 64)
    #pragma unroll
    for (int t = 0; t < 2; t++) {
        int idx4 = tid + t * 256;
        int r    = idx4 >> 4;
        int c4   = idx4 & 15;
        float4 q4 = *(const float4*)(Qp + (size_t)(qBase + r) * DKH + c4 * 4);
        *(float4*)&Qs[r][c4 * 4] = q4;
    }
    if (tid < BM) { m_s[tid] = -1e30f; l_s[tid] = 0.f; }

    float acc[4][16];
    #pragma unroll
    for (int i = 0; i < 4; i++)
        #pragma unroll
        for (int j = 0; j < 16; j++) acc[i][j] = 0.f;

    // Prefetch tile 0 into registers
    float4 kreg;
    float4 vreg[8];
    {
        int kk = tid >> 4, c4 = tid & 15;
        kreg = *(const float4*)(Kp + (size_t)kk * DKH + c4 * 4);
        #pragma unroll
        for (int t = 0; t < 8; t++) {
            int idx4 = tid + t * 256;
            int vk = idx4 >> 7, vc = idx4 & 127;
            vreg[t] = *(const float4*)(Vp + (size_t)vk * CIN + vc * 4);
        }
    }

    for (int kb = 0; kb < NTOK; kb += BN) {
        // Commit staged K/V tile to smem
        {
            int kk = tid >> 4, c4 = tid & 15;
            *(float4*)&Ks[kk][c4 * 4] = kreg;
            #pragma unroll
            for (int t = 0; t < 8; t++) {
                int idx4 = tid + t * 256;
                int vk = idx4 >> 7, vc = idx4 & 127;
                *(float4*)&Vs[vk][vc * 4] = vreg[t];
            }
        }
        __syncthreads();

        // Prefetch next tile (overlaps with compute below)
        int nb = kb + BN;
        if (nb < NTOK) {
            int kk = tid >> 4, c4 = tid & 15;
            kreg = *(const float4*)(Kp + (size_t)(nb + kk) * DKH + c4 * 4);
            #pragma unroll
            for (int t = 0; t < 8; t++) {
                int idx4 = tid + t * 256;
                int vk = idx4 >> 7, vc = idx4 & 127;
                vreg[t] = *(const float4*)(Vp + (size_t)(nb + vk) * CIN + vc * 4);
            }
        }

        // Stage A: scores S[32][16] (2 dot-products of length 64 per thread)
        #pragma unroll
        for (int s = tid; s < BM * BN; s += 256) {
            int row = s >> 4;
            int key = s & 15;
            const float4* q4 = (const float4*)&Qs[row][0];
            const float4* k4 = (const float4*)&Ks[key][0];
            float d = 0.f;
            #pragma unroll
            for (int i = 0; i < 16; i++) {
                float4 qv = q4[i], kv = k4[i];
                d = fmaf(qv.x, kv.x, d);
                d = fmaf(qv.y, kv.y, d);
                d = fmaf(qv.z, kv.z, d);
                d = fmaf(qv.w, kv.w, d);
            }
            Ss[row][key] = d;
        }
        __syncthreads();

        // Stage B: per-row online softmax update (one thread per row)
        if (tid < BM) {
            float mold = m_s[tid];
            float mx   = mold;
            float sv[BN];
            #pragma unroll
            for (int kk2 = 0; kk2 < BN; kk2++) { sv[kk2] = Ss[tid][kk2]; mx = fmaxf(mx, sv[kk2]); }
            float corr = __expf(mold - mx);
            float sum  = 0.f;
            #pragma unroll
            for (int kk2 = 0; kk2 < BN; kk2++) {
                float p = __expf(sv[kk2] - mx);
                Ss[tid][kk2] = p;   // S becomes P in place
                sum += p;
            }
            l_s[tid]    = l_s[tid] * corr + sum;
            m_s[tid]    = mx;
            corr_s[tid] = corr;
        }
        __syncthreads();

        // Stage C: rescale acc, then acc += P[4,16] @ V[16, owned cols]
        {
            float c0 = corr_s[rg * 4 + 0], c1 = corr_s[rg * 4 + 1];
            float c2 = corr_s[rg * 4 + 2], c3 = corr_s[rg * 4 + 3];
            #pragma unroll
            for (int j = 0; j < 16; j++) {
                acc[0][j] *= c0; acc[1][j] *= c1; acc[2][j] *= c2; acc[3][j] *= c3;
            }
            #pragma unroll 4
            for (int kk = 0; kk < BN; kk++) {
                float p0 = Ss[rg * 4 + 0][kk];
                float p1 = Ss[rg * 4 + 1][kk];
                float p2 = Ss[rg * 4 + 2][kk];
                float p3 = Ss[rg * 4 + 3][kk];
                #pragma unroll
                for (int j = 0; j < 16; j++) {
                    float vv = Vs[kk][lane + 32 * j];   // bank = lane: conflict-free
                    acc[0][j] = fmaf(p0, vv, acc[0][j]);
                    acc[1][j] = fmaf(p1, vv, acc[1][j]);
                    acc[2][j] = fmaf(p2, vv, acc[2][j]);
                    acc[3][j] = fmaf(p3, vv, acc[3][j]);
                }
            }
        }
        __syncthreads();
    }

    // Epilogue: normalize, add residual, coalesced store
    #pragma unroll
    for (int i = 0; i < 4; i++) {
        int   row = qBase + rg * 4 + i;
        float inv = 1.0f / l_s[rg * 4 + i];
        #pragma unroll
        for (int j = 0; j < 16; j++) {
            int col = lane + 32 * j;
            out[(size_t)row * CIN + col] =
                fmaf(acc[i][j], inv, resid[(size_t)row * CIN + col]);
        }
    }
}

extern "C" void kernel_launch(void* const* d_in, const int* in_sizes, int n_in,
                              void* d_out, int out_size) {
    const float* im1 = (const float*)d_in[0];
    const float* im2 = (const float*)d_in[1];
    const float* Wq  = (const float*)d_in[2];
    const float* Wk  = (const float*)d_in[3];
    const float* Wv  = (const float*)d_in[4];
    float* out = (float*)d_out;

    dim3 pgrid(NTOK / 64, PCOLS / 64, 2);
    proj_kernel<<<pgrid, 256>>>(im1, im2, Wq, Wk, Wv);

    dim3 agrid(NTOK / BM, 2);
    attn_kernel<<<agrid, 256>>>(im1, im2, out);
}

// round 7
// speedup vs baseline: 1.0008x; 1.0008x over previous
#include <cuda_runtime.h>
#include <cuda_bf16.h>

#define NTOK 8192
#define CIN 512
#define DKH 64
#define BM 32
#define BN 16
#define PCOLS 640

// Scratch for projected Q/K/V (static device memory; no runtime allocation).
__device__ float g_q[2][NTOK * DKH];   // 2 x 2 MB
__device__ float g_k[2][NTOK * DKH];   // 2 x 2 MB
__device__ float g_v[2][NTOK * CIN];   // 2 x 16 MB

// ---------------------------------------------------------------------------
// Kernel 1: fused QKV projection. C = A[16384? no: per-image 8192,512] @ B[512,640]
// where B columns [0,64)=Wq, [64,128)=Wk, [128,640)=Wv. 64x64 output tiles.
// ---------------------------------------------------------------------------
__global__ __launch_bounds__(256, 2)
void proj_kernel(const float* __restrict__ im1, const float* __restrict__ im2,
                 const float* __restrict__ Wq, const float* __restrict__ Wk,
                 const float* __restrict__ Wv) {
    const int img = blockIdx.z;
    const float* __restrict__ A = img ? im2 : im1;
    float* __restrict__ q = g_q[img];
    float* __restrict__ k = g_k[img];
    float* __restrict__ v = g_v[img];

    __shared__ float As[64][17];
    __shared__ float Bs[16][65];

    const int tid = threadIdx.x;
    const int tx = tid & 15;
    const int ty = tid >> 4;
    const int rowBase = blockIdx.x * 64;
    const int colBase = blockIdx.y * 64;

    float acc[4][4] = {};

    for (int kt = 0; kt < CIN; kt += 16) {
        {   // A tile: 64 rows x 16 k, float4 per thread
            int r  = tid >> 2;
            int kk = (tid & 3) << 2;
            float4 a4 = *(const float4*)(A + (size_t)(rowBase + r) * CIN + kt + kk);
            As[r][kk] = a4.x; As[r][kk + 1] = a4.y; As[r][kk + 2] = a4.z; As[r][kk + 3] = a4.w;
        }
        {   // B tile: 16 k x 64 cols (branch is uniform per block)
            int kk   = tid >> 4;
            int c0   = (tid & 15) << 2;
            int kidx = kt + kk;
            #pragma unroll
            for (int j = 0; j < 4; j++) {
                int c = colBase + c0 + j;
                float w;
                if (c < 64)        w = Wq[kidx * DKH + c];
                else if (c < 128)  w = Wk[kidx * DKH + (c - 64)];
                else               w = Wv[kidx * CIN + (c - 128)];
                Bs[kk][c0 + j] = w;
            }
        }
        __syncthreads();
        #pragma unroll
        for (int kk = 0; kk < 16; kk++) {
            float a[4], b[4];
            #pragma unroll
            for (int i = 0; i < 4; i++) a[i] = As[ty * 4 + i][kk];
            #pragma unroll
            for (int j = 0; j < 4; j++) b[j] = Bs[kk][tx * 4 + j];
            #pragma unroll
            for (int i = 0; i < 4; i++)
                #pragma unroll
                for (int j = 0; j < 4; j++)
                    acc[i][j] = fmaf(a[i], b[j], acc[i][j]);
        }
        __syncthreads();
    }

    #pragma unroll
    for (int i = 0; i < 4; i++) {
        int row = rowBase + ty * 4 + i;
        #pragma unroll
        for (int j = 0; j < 4; j++) {
            int c = colBase + tx * 4 + j;
            float val = acc[i][j];
            if (c < 64)        q[row * DKH + c] = val;
            else if (c < 128)  k[row * DKH + (c - 64)] = val;
            else               v[row * CIN + (c - 128)] = val;
        }
    }
}

// ---------------------------------------------------------------------------
// Kernel 2: flash attention + residual.
// side=0: im1_out = softmax(q2 @ k1^T) @ v1 + im1
// side=1: im2_out = softmax(q1 @ k2^T) @ v2 + im2
// CTA: BM=32 query rows, 256 threads. Thread (rg=tid/32, lane=tid%32) owns
// rows rg*4..rg*4+3 and columns {lane + 32*j} (j=0..15) of the [32,512] acc.
// ---------------------------------------------------------------------------
__global__ __launch_bounds__(256, 2)
void attn_kernel(const float* __restrict__ im1, const float* __restrict__ im2,
                 float* __restrict__ out_all) {
    const int side = blockIdx.y;
    const float* __restrict__ Qp    = g_q[side ? 0 : 1];  // cross: out1 uses im2_q
    const float* __restrict__ Kp    = g_k[side ? 1 : 0];
    const float* __restrict__ Vp    = g_v[side ? 1 : 0];
    const float* __restrict__ resid = side ? im2 : im1;
    float* __restrict__ out = out_all + (size_t)side * NTOK * CIN;

    __shared__ float Qs[BM][68];
    __shared__ float Ks[BN][68];
    __shared__ float Vs[BN][CIN];
    __shared__ float Ss[BM][17];
    __shared__ float m_s[BM], l_s[BM], corr_s[BM];

    const int tid   = threadIdx.x;
    const int lane  = tid & 31;
    const int rg    = tid >> 5;
    const int qBase = blockIdx.x * BM;

    // Load Q tile once (32 x 64)
    #pragma unroll
    for (int t = 0; t < 2; t++) {
        int idx4 = tid + t * 256;
        int r    = idx4 >> 4;
        int c4   = idx4 & 15;
        float4 q4 = *(const float4*)(Qp + (size_t)(qBase + r) * DKH + c4 * 4);
        *(float4*)&Qs[r][c4 * 4] = q4;
    }
    if (tid < BM) { m_s[tid] = -1e30f; l_s[tid] = 0.f; }

    float acc[4][16];
    #pragma unroll
    for (int i = 0; i < 4; i++)
        #pragma unroll
        for (int j = 0; j < 16; j++) acc[i][j] = 0.f;

    // Prefetch tile 0 into registers
    float4 kreg;
    float4 vreg[8];
    {
        int kk = tid >> 4, c4 = tid & 15;
        kreg = *(const float4*)(Kp + (size_t)kk * DKH + c4 * 4);
        #pragma unroll
        for (int t = 0; t < 8; t++) {
            int idx4 = tid + t * 256;
            int vk = idx4 >> 7, vc = idx4 & 127;
            vreg[t] = *(const float4*)(Vp + (size_t)vk * CIN + vc * 4);
        }
    }

    for (int kb = 0; kb < NTOK; kb += BN) {
        // Commit staged K/V tile to smem
        {
            int kk = tid >> 4, c4 = tid & 15;
            *(float4*)&Ks[kk][c4 * 4] = kreg;
            #pragma unroll
            for (int t = 0; t < 8; t++) {
                int idx4 = tid + t * 256;
                int vk = idx4 >> 7, vc = idx4 & 127;
                *(float4*)&Vs[vk][vc * 4] = vreg[t];
            }
        }
        __syncthreads();

        // Prefetch next tile (overlaps with compute below)
        int nb = kb + BN;
        if (nb < NTOK) {
            int kk = tid >> 4, c4 = tid & 15;
            kreg = *(const float4*)(Kp + (size_t)(nb + kk) * DKH + c4 * 4);
            #pragma unroll
            for (int t = 0; t < 8; t++) {
                int idx4 = tid + t * 256;
                int vk = idx4 >> 7, vc = idx4 & 127;
                vreg[t] = *(const float4*)(Vp + (size_t)(nb + vk) * CIN + vc * 4);
            }
        }

        // Stage A: scores S[32][16] (2 dot-products of length 64 per thread)
        #pragma unroll
        for (int s = tid; s < BM * BN; s += 256) {
            int row = s >> 4;
            int key = s & 15;
            const float4* q4 = (const float4*)&Qs[row][0];
            const float4* k4 = (const float4*)&Ks[key][0];
            float d = 0.f;
            #pragma unroll
            for (int i = 0; i < 16; i++) {
                float4 qv = q4[i], kv = k4[i];
                d = fmaf(qv.x, kv.x, d);
                d = fmaf(qv.y, kv.y, d);
                d = fmaf(qv.z, kv.z, d);
                d = fmaf(qv.w, kv.w, d);
            }
            Ss[row][key] = d;
        }
        __syncthreads();

        // Stage B: per-row online softmax update (one thread per row)
        if (tid < BM) {
            float mold = m_s[tid];
            float mx   = mold;
            float sv[BN];
            #pragma unroll
            for (int kk2 = 0; kk2 < BN; kk2++) { sv[kk2] = Ss[tid][kk2]; mx = fmaxf(mx, sv[kk2]); }
            float corr = __expf(mold - mx);
            float sum  = 0.f;
            #pragma unroll
            for (int kk2 = 0; kk2 < BN; kk2++) {
                float p = __expf(sv[kk2] - mx);
                Ss[tid][kk2] = p;   // S becomes P in place
                sum += p;
            }
            l_s[tid]    = l_s[tid] * corr + sum;
            m_s[tid]    = mx;
            corr_s[tid] = corr;
        }
        __syncthreads();

        // Stage C: rescale acc, then acc += P[4,16] @ V[16, owned cols]
        {
            float c0 = corr_s[rg * 4 + 0], c1 = corr_s[rg * 4 + 1];
            float c2 = corr_s[rg * 4 + 2], c3 = corr_s[rg * 4 + 3];
            #pragma unroll
            for (int j = 0; j < 16; j++) {
                acc[0][j] *= c0; acc[1][j] *= c1; acc[2][j] *= c2; acc[3][j] *= c3;
            }
            #pragma unroll 4
            for (int kk = 0; kk < BN; kk++) {
                float p0 = Ss[rg * 4 + 0][kk];
                float p1 = Ss[rg * 4 + 1][kk];
                float p2 = Ss[rg * 4 + 2][kk];
                float p3 = Ss[rg * 4 + 3][kk];
                #pragma unroll
                for (int j = 0; j < 16; j++) {
                    float vv = Vs[kk][lane + 32 * j];   // bank = lane: conflict-free
                    acc[0][j] = fmaf(p0, vv, acc[0][j]);
                    acc[1][j] = fmaf(p1, vv, acc[1][j]);
                    acc[2][j] = fmaf(p2, vv, acc[2][j]);
                    acc[3][j] = fmaf(p3, vv, acc[3][j]);
                }
            }
        }
        __syncthreads();
    }

    // Epilogue: normalize, add residual, coalesced store
    #pragma unroll
    for (int i = 0; i < 4; i++) {
        int   row = qBase + rg * 4 + i;
        float inv = 1.0f / l_s[rg * 4 + i];
        #pragma unroll
        for (int j = 0; j < 16; j++) {
            int col = lane + 32 * j;
            out[(size_t)row * CIN + col] =
                fmaf(acc[i][j], inv, resid[(size_t)row * CIN + col]);
        }
    }
}

extern "C" void kernel_launch(void* const* d_in, const int* in_sizes, int n_in,
                              void* d_out, int out_size) {
    const float* im1 = (const float*)d_in[0];
    const float* im2 = (const float*)d_in[1];
    const float* Wq  = (const float*)d_in[2];
    const float* Wk  = (const float*)d_in[3];
    const float* Wv  = (const float*)d_in[4];
    float* out = (float*)d_out;

    dim3 pgrid(NTOK / 64, PCOLS / 64, 2);
    proj_kernel<<<pgrid, 256>>>(im1, im2, Wq, Wk, Wv);

    dim3 agrid(NTOK / BM, 2);
    attn_kernel<<<agrid, 256>>>(im1, im2, out);
}

// round 9
// speedup vs baseline: 6.8130x; 6.8075x over previous
#include <cuda_runtime.h>
#include <cuda_fp16.h>
#include <cstdint>

#define NTOK 8192
#define CIN 512
#define DK 64
#define BM 64            // queries per CTA
#define BN 64            // keys per iteration
#define ITERS (NTOK / BN)
#define PCOLS 640

// ---------------- static scratch (fp16 operands) ----------------
__device__ __align__(16) __half g_qh[2][NTOK * DK];
__device__ __align__(16) __half g_ql[2][NTOK * DK];
__device__ __align__(16) __half g_kh[2][NTOK * DK];
__device__ __align__(16) __half g_kl[2][NTOK * DK];
__device__ __align__(16) __half g_vh[2][(size_t)NTOK * CIN];

// ---------------- smem layout (attn kernel) ----------------
#define SM_MROW  0                       // float[64]
#define SM_CORR  256                     // float[64]
#define SM_PMAX  512                     // float[4][64] (reused as lsum)
#define SM_QH    2048                    // 64 x 128B swizzled
#define SM_QL    (SM_QH + 8192)
#define SM_KH(b) (18432 + (b) * 16384)
#define SM_KL(b) (26624 + (b) * 16384)
#define SM_V(b)  (51200 + (b) * 65536)   // 64 x 1024B swizzled
#define SM_P     182272                  // 64 x 128B swizzled
#define SM_TOTAL 190464

// ---------------- PTX helpers (base ISA only: sm_80-era) ----------------
__device__ __forceinline__ uint32_t smem_u32(const void* p) {
    uint32_t a;
    asm("{ .reg .u64 t; cvta.to.shared.u64 t, %1; cvt.u32.u64 %0, t; }" : "=r"(a) : "l"(p));
    return a;
}
__device__ __forceinline__ void mma16816(float* c, const uint32_t* a, uint32_t b0, uint32_t b1) {
    asm volatile(
        "mma.sync.aligned.m16n8k16.row.col.f32.f16.f16.f32 "
        "{%0,%1,%2,%3}, {%4,%5,%6,%7}, {%8,%9}, {%0,%1,%2,%3};"
        : "+f"(c[0]), "+f"(c[1]), "+f"(c[2]), "+f"(c[3])
        : "r"(a[0]), "r"(a[1]), "r"(a[2]), "r"(a[3]), "r"(b0), "r"(b1));
}
__device__ __forceinline__ void ldsm4(uint32_t* d, uint32_t addr) {
    asm volatile("ldmatrix.sync.aligned.m8n8.x4.shared.b16 {%0,%1,%2,%3}, [%4];"
                 : "=r"(d[0]), "=r"(d[1]), "=r"(d[2]), "=r"(d[3]) : "r"(addr));
}
__device__ __forceinline__ void ldsm4t(uint32_t* d, uint32_t addr) {
    asm volatile("ldmatrix.sync.aligned.m8n8.x4.trans.shared.b16 {%0,%1,%2,%3}, [%4];"
                 : "=r"(d[0]), "=r"(d[1]), "=r"(d[2]), "=r"(d[3]) : "r"(addr));
}
#define CP16(dst, src)  asm volatile("cp.async.cg.shared.global [%0], [%1], 16;" :: "r"(dst), "l"(src))
#define CPCOMMIT()      asm volatile("cp.async.commit_group;" ::: "memory")
#define CPWAIT1()       asm volatile("cp.async.wait_group 1;" ::: "memory")

// ---------------------------------------------------------------------------
// Kernel 1: fused QKV projection. q,k -> fp16 hi/lo; v -> fp16.
// ---------------------------------------------------------------------------
__global__ __launch_bounds__(256, 2)
void proj_kernel(const float* __restrict__ im1, const float* __restrict__ im2,
                 const float* __restrict__ Wq, const float* __restrict__ Wk,
                 const float* __restrict__ Wv) {
    const int img = blockIdx.z;
    const float* __restrict__ A = img ? im2 : im1;

    __shared__ float As[64][17];
    __shared__ float Bs[16][65];

    const int tid = threadIdx.x;
    const int tx = tid & 15;
    const int ty = tid >> 4;
    const int rowBase = blockIdx.x * 64;
    const int colBase = blockIdx.y * 64;

    float acc[4][4] = {};

    for (int kt = 0; kt < CIN; kt += 16) {
        {
            int r  = tid >> 2;
            int kk = (tid & 3) << 2;
            float4 a4 = *(const float4*)(A + (size_t)(rowBase + r) * CIN + kt + kk);
            As[r][kk] = a4.x; As[r][kk + 1] = a4.y; As[r][kk + 2] = a4.z; As[r][kk + 3] = a4.w;
        }
        {
            int kk   = tid >> 4;
            int c0   = (tid & 15) << 2;
            int kidx = kt + kk;
            #pragma unroll
            for (int j = 0; j < 4; j++) {
                int c = colBase + c0 + j;
                float w;
                if (c < 64)        w = Wq[kidx * DK + c];
                else if (c < 128)  w = Wk[kidx * DK + (c - 64)];
                else               w = Wv[kidx * CIN + (c - 128)];
                Bs[kk][c0 + j] = w;
            }
        }
        __syncthreads();
        #pragma unroll
        for (int kk = 0; kk < 16; kk++) {
            float a[4], b[4];
            #pragma unroll
            for (int i = 0; i < 4; i++) a[i] = As[ty * 4 + i][kk];
            #pragma unroll
            for (int j = 0; j < 4; j++) b[j] = Bs[kk][tx * 4 + j];
            #pragma unroll
            for (int i = 0; i < 4; i++)
                #pragma unroll
                for (int j = 0; j < 4; j++)
                    acc[i][j] = fmaf(a[i], b[j], acc[i][j]);
        }
        __syncthreads();
    }

    #pragma unroll
    for (int i = 0; i < 4; i++) {
        int row = rowBase + ty * 4 + i;
        #pragma unroll
        for (int j = 0; j < 4; j++) {
            int c = colBase + tx * 4 + j;
            float val = acc[i][j];
            if (c < 64) {
                __half h = __float2half_rn(val);
                g_qh[img][row * DK + c] = h;
                g_ql[img][row * DK + c] = __float2half_rn(val - __half2float(h));
            } else if (c < 128) {
                __half h = __float2half_rn(val);
                g_kh[img][row * DK + (c - 64)] = h;
                g_kl[img][row * DK + (c - 64)] = __float2half_rn(val - __half2float(h));
            } else {
                g_vh[img][(size_t)row * CIN + (c - 128)] = __float2half_rn(val);
            }
        }
    }
}

// ---------------------------------------------------------------------------
// cp.async loaders
// ---------------------------------------------------------------------------
__device__ __forceinline__ void load_kv(uint32_t SB, const __half* Kh, const __half* Kl,
                                        const __half* Vh, int kb, int buf, int tid) {
    int r = tid >> 3, c = tid & 7;
    uint32_t sw = (uint32_t)((c ^ (r & 7)) * 16);
    CP16(SB + SM_KH(buf) + r * 128 + sw, Kh + (size_t)(kb + r) * DK + c * 8);
    CP16(SB + SM_KL(buf) + r * 128 + sw, Kl + (size_t)(kb + r) * DK + c * 8);
    #pragma unroll
    for (int i = 0; i < 8; i++) {
        int idx = tid + i * 512;
        int vr = idx >> 6, vc = idx & 63;
        CP16(SB + SM_V(buf) + vr * 1024 + (uint32_t)((vc ^ (vr & 7)) * 16),
             Vh + (size_t)(kb + vr) * CIN + vc * 8);
    }
}

// ---------------------------------------------------------------------------
// Kernel 2: HMMA flash attention + residual. grid (128 qblocks, 2 sides), 512 thr.
// ---------------------------------------------------------------------------
__global__ __launch_bounds__(512, 1)
void attn_kernel(const float* __restrict__ im1, const float* __restrict__ im2,
                 float* __restrict__ out_all) {
    extern __shared__ char smem[];
    const uint32_t SB = smem_u32(smem);
    float* const stats = (float*)smem;

    const int tid  = threadIdx.x;
    const int warp = tid >> 5;
    const int lane = tid & 31;
    const int side  = blockIdx.y;
    const int qBase = blockIdx.x * BM;

    const __half* __restrict__ Qh = g_qh[side ^ 1];
    const __half* __restrict__ Ql = g_ql[side ^ 1];
    const __half* __restrict__ Kh = g_kh[side];
    const __half* __restrict__ Kl = g_kl[side];
    const __half* __restrict__ Vh = g_vh[side];
    const float* __restrict__ resid = side ? im2 : im1;
    float* __restrict__ out = out_all + (size_t)side * NTOK * CIN;

    const int rg = warp & 3;          // row group (16 rows)
    const int kg = warp >> 2;         // key group (16 keys) for S / channel group (128) for PV
    const int rows0 = rg * 16;
    const int key0  = kg * 16;
    const int ch0   = kg * 128;

    const int l7  = lane & 7;
    const int l8  = (lane >> 3) & 1;
    const int l16 = lane >> 4;
    const int lq  = lane >> 2;        // row-quad id
    const int lc  = lane & 3;
    const int row_a = rows0 + lq;
    const int row_b = row_a + 8;

    // ldmatrix fragment addresses
    auto frag128 = [&](uint32_t base, int row0, int ks) -> uint32_t {
        int r  = row0 + l7 + l8 * 8;
        int ch = ks * 2 + l16;
        return SB + base + r * 128 + (uint32_t)(((ch ^ (r & 7)) & 7) * 16);
    };
    auto fragV = [&](int buf, int k0, int n0) -> uint32_t {
        int r  = k0 + l7 + l8 * 8;
        int ch = (n0 >> 3) + l16;
        return SB + SM_V(buf) + r * 1024 + (uint32_t)((ch ^ (r & 7)) * 16);
    };

    // ---- prologue: Q (once) + K/V tiles 0,1 ----
    {
        int r = tid >> 3, c = tid & 7;
        uint32_t sw = (uint32_t)((c ^ (r & 7)) * 16);
        CP16(SB + SM_QH + r * 128 + sw, Qh + (size_t)(qBase + r) * DK + c * 8);
        CP16(SB + SM_QL + r * 128 + sw, Ql + (size_t)(qBase + r) * DK + c * 8);
        load_kv(SB, Kh, Kl, Vh, 0, 0, tid);
        CPCOMMIT();
        load_kv(SB, Kh, Kl, Vh, BN, 1, tid);
        CPCOMMIT();
    }

    float o[16][4];
    #pragma unroll
    for (int j = 0; j < 16; j++)
        #pragma unroll
        for (int i = 0; i < 4; i++) o[j][i] = 0.f;
    float m_reg = -1e30f, l_reg = 0.f;   // valid for tid < 64 (row owner)

    for (int it = 0; it < ITERS; it++) {
        const int b = it & 1;
        CPWAIT1();
        __syncthreads();

        // ---------- Phase A: S[16 rows][16 keys] via 3-term hi/lo mma ----------
        float s[2][4];
        #pragma unroll
        for (int t = 0; t < 2; t++)
            #pragma unroll
            for (int i = 0; i < 4; i++) s[t][i] = 0.f;

        #pragma unroll
        for (int ks = 0; ks < 4; ks++) {
            uint32_t aqh[4], aql[4], bkh[4], bkl[4];
            ldsm4(aqh, frag128(SM_QH, rows0, ks));
            ldsm4(aql, frag128(SM_QL, rows0, ks));
            ldsm4(bkh, frag128(SM_KH(b), key0, ks));
            ldsm4(bkl, frag128(SM_KL(b), key0, ks));
            mma16816(s[0], aqh, bkh[0], bkh[2]);
            mma16816(s[1], aqh, bkh[1], bkh[3]);
            mma16816(s[0], aqh, bkl[0], bkl[2]);
            mma16816(s[1], aqh, bkl[1], bkl[3]);
            mma16816(s[0], aql, bkh[0], bkh[2]);
            mma16816(s[1], aql, bkh[1], bkh[3]);
        }

        // ---------- Phase B: per-row partial max ----------
        float ma = fmaxf(fmaxf(s[0][0], s[0][1]), fmaxf(s[1][0], s[1][1]));
        float mb = fmaxf(fmaxf(s[0][2], s[0][3]), fmaxf(s[1][2], s[1][3]));
        ma = fmaxf(ma, __shfl_xor_sync(0xffffffffu, ma, 1));
        ma = fmaxf(ma, __shfl_xor_sync(0xffffffffu, ma, 2));
        mb = fmaxf(mb, __shfl_xor_sync(0xffffffffu, mb, 1));
        mb = fmaxf(mb, __shfl_xor_sync(0xffffffffu, mb, 2));
        if (lc == 0) {
            stats[(SM_PMAX >> 2) + kg * 64 + row_a] = ma;
            stats[(SM_PMAX >> 2) + kg * 64 + row_b] = mb;
        }
        __syncthreads();

        // ---------- Phase C: row owners update max, publish corr ----------
        if (tid < 64) {
            float mn = m_reg;
            #pragma unroll
            for (int g = 0; g < 4; g++) mn = fmaxf(mn, stats[(SM_PMAX >> 2) + g * 64 + tid]);
            float corr = __expf(m_reg - mn);
            m_reg = mn;
            stats[(SM_MROW >> 2) + tid] = mn;
            stats[(SM_CORR >> 2) + tid] = corr;
        }
        __syncthreads();

        // ---------- Phase D: exp, write P (fp16), partial row sums ----------
        {
            float mA = stats[(SM_MROW >> 2) + row_a];
            float mB = stats[(SM_MROW >> 2) + row_b];
            float la = 0.f, lb = 0.f;
            #pragma unroll
            for (int t = 0; t < 2; t++) {
                float p0 = __expf(s[t][0] - mA);
                float p1 = __expf(s[t][1] - mA);
                float p2 = __expf(s[t][2] - mB);
                float p3 = __expf(s[t][3] - mB);
                la += p0 + p1;
                lb += p2 + p3;
                __half2 hA = __floats2half2_rn(p0, p1);
                __half2 hB = __floats2half2_rn(p2, p3);
                int ch = kg * 2 + t;
                *(uint32_t*)(smem + SM_P + row_a * 128 + ((ch ^ (row_a & 7)) * 16) + lc * 4) =
                    *(uint32_t*)&hA;
                *(uint32_t*)(smem + SM_P + row_b * 128 + ((ch ^ (row_b & 7)) * 16) + lc * 4) =
                    *(uint32_t*)&hB;
            }
            la += __shfl_xor_sync(0xffffffffu, la, 1);
            la += __shfl_xor_sync(0xffffffffu, la, 2);
            lb += __shfl_xor_sync(0xffffffffu, lb, 1);
            lb += __shfl_xor_sync(0xffffffffu, lb, 2);
            if (lc == 0) {
                stats[(SM_PMAX >> 2) + kg * 64 + row_a] = la;   // reuse as lsum
                stats[(SM_PMAX >> 2) + kg * 64 + row_b] = lb;
            }
        }
        __syncthreads();

        // ---------- Phase E/F: l update, acc rescale, PV mma ----------
        if (tid < 64) {
            float ls = 0.f;
            #pragma unroll
            for (int g = 0; g < 4; g++) ls += stats[(SM_PMAX >> 2) + g * 64 + tid];
            l_reg = l_reg * stats[(SM_CORR >> 2) + tid] + ls;
        }
        {
            float ca = stats[(SM_CORR >> 2) + row_a];
            float cb = stats[(SM_CORR >> 2) + row_b];
            if (!__all_sync(0xffffffffu, (ca == 1.0f) && (cb == 1.0f))) {
                #pragma unroll
                for (int j = 0; j < 16; j++) {
                    o[j][0] *= ca; o[j][1] *= ca; o[j][2] *= cb; o[j][3] *= cb;
                }
            }
        }
        #pragma unroll
        for (int ks = 0; ks < 4; ks++) {
            uint32_t ap[4];
            ldsm4(ap, frag128(SM_P, rows0, ks));
            #pragma unroll
            for (int np = 0; np < 8; np++) {
                uint32_t v4[4];
                ldsm4t(v4, fragV(b, ks * 16, ch0 + np * 16));
                mma16816(o[np * 2 + 0], ap, v4[0], v4[1]);
                mma16816(o[np * 2 + 1], ap, v4[2], v4[3]);
            }
        }
        __syncthreads();

        // ---------- prefetch it+2 into buffer b ----------
        if (it + 2 < ITERS) load_kv(SB, Kh, Kl, Vh, (it + 2) * BN, b, tid);
        CPCOMMIT();
    }

    // ---------- epilogue ----------
    if (tid < 64) stats[(SM_CORR >> 2) + tid] = 1.0f / l_reg;
    __syncthreads();
    {
        float ia = stats[(SM_CORR >> 2) + row_a];
        float ib = stats[(SM_CORR >> 2) + row_b];
        const size_t ra = (size_t)(qBase + row_a) * CIN;
        const size_t rb = (size_t)(qBase + row_b) * CIN;
        #pragma unroll
        for (int j = 0; j < 16; j++) {
            int c = ch0 + j * 8 + lc * 2;
            float2 r2 = *(const float2*)(resid + ra + c);
            float2 w2 = make_float2(fmaf(o[j][0], ia, r2.x), fmaf(o[j][1], ia, r2.y));
            *(float2*)(out + ra + c) = w2;
            float2 r3 = *(const float2*)(resid + rb + c);
            float2 w3 = make_float2(fmaf(o[j][2], ib, r3.x), fmaf(o[j][3], ib, r3.y));
            *(float2*)(out + rb + c) = w3;
        }
    }
}

extern "C" void kernel_launch(void* const* d_in, const int* in_sizes, int n_in,
                              void* d_out, int out_size) {
    const float* im1 = (const float*)d_in[0];
    const float* im2 = (const float*)d_in[1];
    const float* Wq  = (const float*)d_in[2];
    const float* Wk  = (const float*)d_in[3];
    const float* Wv  = (const float*)d_in[4];
    float* out = (float*)d_out;

    cudaFuncSetAttribute(attn_kernel, cudaFuncAttributeMaxDynamicSharedMemorySize, SM_TOTAL);

    dim3 pgrid(NTOK / 64, PCOLS / 64, 2);
    proj_kernel<<<pgrid, 256>>>(im1, im2, Wq, Wk, Wv);

    dim3 agrid(NTOK / BM, 2);
    attn_kernel<<<agrid, 512, SM_TOTAL>>>(im1, im2, out);
}

// round 10
// speedup vs baseline: 9.5331x; 1.3992x over previous
#include <cuda_runtime.h>
#include <cuda_fp16.h>
#include <cstdint>

#define NTOK 8192
#define CIN 512
#define DK 64
#define BM 64            // queries per CTA (attn)
#define BN 64            // keys per iteration
#define ITERS (NTOK / BN)
#define PCOLS 640

// ---------------- static scratch (fp16 operands) ----------------
__device__ __align__(16) __half g_qh[2][NTOK * DK];
__device__ __align__(16) __half g_ql[2][NTOK * DK];
__device__ __align__(16) __half g_kh[2][NTOK * DK];
__device__ __align__(16) __half g_kl[2][NTOK * DK];
__device__ __align__(16) __half g_vh[2][(size_t)NTOK * CIN];

// ---------------- PTX helpers (base ISA only) ----------------
__device__ __forceinline__ uint32_t smem_u32(const void* p) {
    uint32_t a;
    asm("{ .reg .u64 t; cvta.to.shared.u64 t, %1; cvt.u32.u64 %0, t; }" : "=r"(a) : "l"(p));
    return a;
}
__device__ __forceinline__ void mma16816(float* c, const uint32_t* a, uint32_t b0, uint32_t b1) {
    asm volatile(
        "mma.sync.aligned.m16n8k16.row.col.f32.f16.f16.f32 "
        "{%0,%1,%2,%3}, {%4,%5,%6,%7}, {%8,%9}, {%0,%1,%2,%3};"
        : "+f"(c[0]), "+f"(c[1]), "+f"(c[2]), "+f"(c[3])
        : "r"(a[0]), "r"(a[1]), "r"(a[2]), "r"(a[3]), "r"(b0), "r"(b1));
}
__device__ __forceinline__ void ldsm4(uint32_t* d, uint32_t addr) {
    asm volatile("ldmatrix.sync.aligned.m8n8.x4.shared.b16 {%0,%1,%2,%3}, [%4];"
                 : "=r"(d[0]), "=r"(d[1]), "=r"(d[2]), "=r"(d[3]) : "r"(addr));
}
__device__ __forceinline__ void ldsm4t(uint32_t* d, uint32_t addr) {
    asm volatile("ldmatrix.sync.aligned.m8n8.x4.trans.shared.b16 {%0,%1,%2,%3}, [%4];"
                 : "=r"(d[0]), "=r"(d[1]), "=r"(d[2]), "=r"(d[3]) : "r"(addr));
}
#define CP16(dst, src)  asm volatile("cp.async.cg.shared.global [%0], [%1], 16;" :: "r"(dst), "l"(src))
#define CPCOMMIT()      asm volatile("cp.async.commit_group;" ::: "memory")
#define CPWAIT1()       asm volatile("cp.async.wait_group 1;" ::: "memory")

// ---------------------------------------------------------------------------
// Kernel 1: HMMA QKV projection. C[8192,640] = A[8192,512] @ W, hi/lo fp16 3-term.
// CTA: 128 rows x 64 cols, 256 threads (8 warps: 4 row-tiles x 2 col-halves).
// ---------------------------------------------------------------------------
__global__ __launch_bounds__(256, 2)
void proj_kernel(const float* __restrict__ im1, const float* __restrict__ im2,
                 const float* __restrict__ Wq, const float* __restrict__ Wk,
                 const float* __restrict__ Wv) {
    const int img = blockIdx.z;
    const float* __restrict__ A = img ? im2 : im1;
    const int rowBase = blockIdx.x * 128;
    const int colBase = blockIdx.y * 64;

    __shared__ __align__(16) __half Ah[128 * 32];   // 64B rows, swizzle chunk^(r&3)
    __shared__ __align__(16) __half Al[128 * 32];
    __shared__ __align__(16) __half Wh[32 * 64];    // 128B rows, swizzle chunk^(r&7)
    __shared__ __align__(16) __half Wl[32 * 64];

    const int tid = threadIdx.x, warp = tid >> 5, lane = tid & 31;
    const int wr = warp & 3, wc = warp >> 2;
    const int l7 = lane & 7, l8 = (lane >> 3) & 1, l16 = lane >> 4;
    const int lq = lane >> 2, lc = lane & 3;

    const uint32_t sAh = smem_u32(Ah), sAl = smem_u32(Al);
    const uint32_t sWh = smem_u32(Wh), sWl = smem_u32(Wl);

    float o[2][4][4] = {};
    float4 aR[4];
    float4 wR[2];

    auto loadA = [&](int kt) {
        #pragma unroll
        for (int i = 0; i < 4; i++) {
            int idx = tid + i * 256;              // 0..1023
            int r = idx >> 3, c4 = idx & 7;
            aR[i] = *(const float4*)(A + (size_t)(rowBase + r) * CIN + kt * 32 + c4 * 4);
        }
    };
    auto loadW = [&](int kt) {
        #pragma unroll
        for (int i = 0; i < 2; i++) {
            int idx = tid + i * 256;              // 0..511
            int r = idx >> 4, c4 = idx & 15;
            int krow = kt * 32 + r;
            int c = colBase + c4 * 4;
            const float* src;
            if (c < 64)       src = Wq + krow * DK + c;
            else if (c < 128) src = Wk + krow * DK + (c - 64);
            else              src = Wv + krow * CIN + (c - 128);
            wR[i] = *(const float4*)src;
        }
    };
    auto splitStore = [&](uint32_t dh, uint32_t dl, float4 v) {
        __half h0 = __float2half_rn(v.x), h1 = __float2half_rn(v.y);
        __half h2 = __float2half_rn(v.z), h3 = __float2half_rn(v.w);
        __half e0 = __float2half_rn(v.x - __half2float(h0));
        __half e1 = __float2half_rn(v.y - __half2float(h1));
        __half e2 = __float2half_rn(v.z - __half2float(h2));
        __half e3 = __float2half_rn(v.w - __half2float(h3));
        __half2 H0 = __halves2half2(h0, h1), H1 = __halves2half2(h2, h3);
        __half2 L0 = __halves2half2(e0, e1), L1 = __halves2half2(e2, e3);
        uint2 hv = make_uint2(*(uint32_t*)&H0, *(uint32_t*)&H1);
        uint2 lv = make_uint2(*(uint32_t*)&L0, *(uint32_t*)&L1);
        *(uint2*)(uintptr_t)dh = hv;   // placeholder (unused)
        *(uint2*)(uintptr_t)dl = lv;
    };
    (void)splitStore;

    loadA(0); loadW(0);

    for (int kt = 0; kt < 16; kt++) {
        // commit staged tiles (convert fp32 -> fp16 hi/lo)
        #pragma unroll
        for (int i = 0; i < 4; i++) {
            int idx = tid + i * 256;
            int r = idx >> 3, c4 = idx & 7;
            uint32_t off = (uint32_t)(r * 64 + (((c4 >> 1) ^ (r & 3)) * 16) + (c4 & 1) * 8);
            float4 v = aR[i];
            __half h0 = __float2half_rn(v.x), h1 = __float2half_rn(v.y);
            __half h2 = __float2half_rn(v.z), h3 = __float2half_rn(v.w);
            __half2 H0 = __halves2half2(h0, h1), H1 = __halves2half2(h2, h3);
            __half2 L0 = __halves2half2(__float2half_rn(v.x - __half2float(h0)),
                                        __float2half_rn(v.y - __half2float(h1)));
            __half2 L1 = __halves2half2(__float2half_rn(v.z - __half2float(h2)),
                                        __float2half_rn(v.w - __half2float(h3)));
            *(uint2*)((char*)Ah + off) = make_uint2(*(uint32_t*)&H0, *(uint32_t*)&H1);
            *(uint2*)((char*)Al + off) = make_uint2(*(uint32_t*)&L0, *(uint32_t*)&L1);
        }
        #pragma unroll
        for (int i = 0; i < 2; i++) {
            int idx = tid + i * 256;
            int r = idx >> 4, c4 = idx & 15;
            uint32_t off = (uint32_t)(r * 128 + (((c4 >> 1) ^ (r & 7)) * 16) + (c4 & 1) * 8);
            float4 v = wR[i];
            __half h0 = __float2half_rn(v.x), h1 = __float2half_rn(v.y);
            __half h2 = __float2half_rn(v.z), h3 = __float2half_rn(v.w);
            __half2 H0 = __halves2half2(h0, h1), H1 = __halves2half2(h2, h3);
            __half2 L0 = __halves2half2(__float2half_rn(v.x - __half2float(h0)),
                                        __float2half_rn(v.y - __half2float(h1)));
            __half2 L1 = __halves2half2(__float2half_rn(v.z - __half2float(h2)),
                                        __float2half_rn(v.w - __half2float(h3)));
            *(uint2*)((char*)Wh + off) = make_uint2(*(uint32_t*)&H0, *(uint32_t*)&H1);
            *(uint2*)((char*)Wl + off) = make_uint2(*(uint32_t*)&L0, *(uint32_t*)&L1);
        }
        __syncthreads();

        if (kt + 1 < 16) { loadA(kt + 1); loadW(kt + 1); }

        #pragma unroll
        for (int ks = 0; ks < 2; ks++) {
            uint32_t wh[2][4], wl[2][4];
            #pragma unroll
            for (int nt = 0; nt < 2; nt++) {
                int rr = ks * 16 + l7 + l8 * 8;
                uint32_t chunk = (uint32_t)((wc * 4 + nt * 2 + l16) ^ (rr & 7));
                ldsm4t(wh[nt], sWh + rr * 128 + chunk * 16);
                ldsm4t(wl[nt], sWl + rr * 128 + chunk * 16);
            }
            #pragma unroll
            for (int rt = 0; rt < 2; rt++) {
                int ar = wr * 32 + rt * 16 + l7 + l8 * 8;
                uint32_t ach = (uint32_t)((ks * 2 + l16) ^ (ar & 3));
                uint32_t ah[4], al[4];
                ldsm4(ah, sAh + ar * 64 + ach * 16);
                ldsm4(al, sAl + ar * 64 + ach * 16);
                #pragma unroll
                for (int nt = 0; nt < 2; nt++) {
                    mma16816(o[rt][nt * 2 + 0], ah, wh[nt][0], wh[nt][1]);
                    mma16816(o[rt][nt * 2 + 1], ah, wh[nt][2], wh[nt][3]);
                    mma16816(o[rt][nt * 2 + 0], ah, wl[nt][0], wl[nt][1]);
                    mma16816(o[rt][nt * 2 + 1], ah, wl[nt][2], wl[nt][3]);
                    mma16816(o[rt][nt * 2 + 0], al, wh[nt][0], wh[nt][1]);
                    mma16816(o[rt][nt * 2 + 1], al, wh[nt][2], wh[nt][3]);
                }
            }
        }
        __syncthreads();
    }

    // epilogue: branch uniform per CTA (colBase in {0, 64, 128..})
    #pragma unroll
    for (int rt = 0; rt < 2; rt++) {
        #pragma unroll
        for (int n = 0; n < 4; n++) {
            int rowA = rowBase + wr * 32 + rt * 16 + lq;
            int rowB = rowA + 8;
            int cA = wc * 32 + n * 8 + lc * 2;   // 0..63 within tile
            float v0 = o[rt][n][0], v1 = o[rt][n][1];
            float v2 = o[rt][n][2], v3 = o[rt][n][3];
            if (colBase == 0) {
                __half h0 = __float2half_rn(v0), h1 = __float2half_rn(v1);
                __half h2 = __float2half_rn(v2), h3 = __float2half_rn(v3);
                *(__half2*)&g_qh[img][rowA * DK + cA] = __halves2half2(h0, h1);
                *(__half2*)&g_qh[img][rowB * DK + cA] = __halves2half2(h2, h3);
                *(__half2*)&g_ql[img][rowA * DK + cA] =
                    __halves2half2(__float2half_rn(v0 - __half2float(h0)),
                                   __float2half_rn(v1 - __half2float(h1)));
                *(__half2*)&g_ql[img][rowB * DK + cA] =
                    __halves2half2(__float2half_rn(v2 - __half2float(h2)),
                                   __float2half_rn(v3 - __half2float(h3)));
            } else if (colBase == 64) {
                __half h0 = __float2half_rn(v0), h1 = __float2half_rn(v1);
                __half h2 = __float2half_rn(v2), h3 = __float2half_rn(v3);
                *(__half2*)&g_kh[img][rowA * DK + cA] = __halves2half2(h0, h1);
                *(__half2*)&g_kh[img][rowB * DK + cA] = __halves2half2(h2, h3);
                *(__half2*)&g_kl[img][rowA * DK + cA] =
                    __halves2half2(__float2half_rn(v0 - __half2float(h0)),
                                   __float2half_rn(v1 - __half2float(h1)));
                *(__half2*)&g_kl[img][rowB * DK + cA] =
                    __halves2half2(__float2half_rn(v2 - __half2float(h2)),
                                   __float2half_rn(v3 - __half2float(h3)));
            } else {
                int cv = colBase - 128 + cA;
                *(__half2*)&g_vh[img][(size_t)rowA * CIN + cv] =
                    __halves2half2(__float2half_rn(v0), __float2half_rn(v1));
                *(__half2*)&g_vh[img][(size_t)rowB * CIN + cv] =
                    __halves2half2(__float2half_rn(v2), __float2half_rn(v3));
            }
        }
    }
}

// ---------------- attn smem layout ----------------
// stats (float idx): MROW[2][64] @0, CORR[64] @128, PMAX[4][64] @192, PSUM[4][64] @448
#define IX_MROW(cur, row) ((cur) * 64 + (row))
#define IX_CORR(row)      (128 + (row))
#define IX_PMAX(g, row)   (192 + (g) * 64 + (row))
#define IX_PSUM(g, row)   (448 + (g) * 64 + (row))
#define SM_QH    3072
#define SM_QL    (SM_QH + 8192)
#define SM_KH(b) (19456 + (b) * 16384)
#define SM_KL(b) (27648 + (b) * 16384)
#define SM_V(b)  (52224 + (b) * 65536)
#define SM_P     183296
#define SM_TOTAL 191488

__device__ __forceinline__ void load_kv(uint32_t SB, const __half* Kh, const __half* Kl,
                                        const __half* Vh, int kb, int buf, int tid) {
    int r = tid >> 3, c = tid & 7;
    uint32_t sw = (uint32_t)((c ^ (r & 7)) * 16);
    CP16(SB + SM_KH(buf) + r * 128 + sw, Kh + (size_t)(kb + r) * DK + c * 8);
    CP16(SB + SM_KL(buf) + r * 128 + sw, Kl + (size_t)(kb + r) * DK + c * 8);
    #pragma unroll
    for (int i = 0; i < 8; i++) {
        int idx = tid + i * 512;
        int vr = idx >> 6, vc = idx & 63;
        CP16(SB + SM_V(buf) + vr * 1024 + (uint32_t)((vc ^ (vr & 7)) * 16),
             Vh + (size_t)(kb + vr) * CIN + vc * 8);
    }
}

// ---------------------------------------------------------------------------
// Kernel 2: HMMA flash attention + residual. grid (128 qblocks, 2 sides), 512 thr.
// S phase: warp = (rg, kg) 16 rows x 16 keys. PV phase: warp owns 32 channels x 64 rows.
// ---------------------------------------------------------------------------
__global__ __launch_bounds__(512, 1)
void attn_kernel(const float* __restrict__ im1, const float* __restrict__ im2,
                 float* __restrict__ out_all) {
    extern __shared__ char smem[];
    const uint32_t SB = smem_u32(smem);
    float* const stats = (float*)smem;

    const int tid  = threadIdx.x;
    const int warp = tid >> 5;
    const int lane = tid & 31;
    const int side  = blockIdx.y;
    const int qBase = blockIdx.x * BM;

    const __half* __restrict__ Qh = g_qh[side ^ 1];
    const __half* __restrict__ Ql = g_ql[side ^ 1];
    const __half* __restrict__ Kh = g_kh[side];
    const __half* __restrict__ Kl = g_kl[side];
    const __half* __restrict__ Vh = g_vh[side];
    const float* __restrict__ resid = side ? im2 : im1;
    float* __restrict__ out = out_all + (size_t)side * NTOK * CIN;

    const int rg = warp & 3;          // S phase: row group
    const int kg = warp >> 2;         // S phase: key group
    const int rows0 = rg * 16;
    const int key0  = kg * 16;
    const int chW   = warp * 32;      // PV phase: this warp's 32 channels

    const int l7  = lane & 7;
    const int l8  = (lane >> 3) & 1;
    const int l16 = lane >> 4;
    const int lq  = lane >> 2;
    const int lc  = lane & 3;
    const int row_a = rows0 + lq;
    const int row_b = row_a + 8;

    auto frag128 = [&](uint32_t base, int row0, int ks) -> uint32_t {
        int r  = row0 + l7 + l8 * 8;
        int ch = ks * 2 + l16;
        return SB + base + r * 128 + (uint32_t)(((ch ^ (r & 7)) & 7) * 16);
    };
    auto fragV = [&](int buf, int k0, int n0) -> uint32_t {
        int r  = k0 + l7 + l8 * 8;
        int ch = (n0 >> 3) + l16;
        return SB + SM_V(buf) + r * 1024 + (uint32_t)((ch ^ (r & 7)) * 16);
    };

    // ---- prologue ----
    if (tid < 64) stats[IX_MROW(0, tid)] = -1e30f;
    {
        int r = tid >> 3, c = tid & 7;
        uint32_t sw = (uint32_t)((c ^ (r & 7)) * 16);
        CP16(SB + SM_QH + r * 128 + sw, Qh + (size_t)(qBase + r) * DK + c * 8);
        CP16(SB + SM_QL + r * 128 + sw, Ql + (size_t)(qBase + r) * DK + c * 8);
        load_kv(SB, Kh, Kl, Vh, 0, 0, tid);
        CPCOMMIT();
        load_kv(SB, Kh, Kl, Vh, BN, 1, tid);
        CPCOMMIT();
    }

    float o[4][4][4];   // [row-tile][n8 within 32ch][frag]
    #pragma unroll
    for (int rt = 0; rt < 4; rt++)
        #pragma unroll
        for (int n = 0; n < 4; n++)
            #pragma unroll
            for (int i = 0; i < 4; i++) o[rt][n][i] = 0.f;
    float l_reg = 0.f, corr_loc = 1.f;   // valid for tid < 64

    for (int it = 0; it < ITERS; it++) {
        const int b   = it & 1;
        const int cur = it & 1, nxt = cur ^ 1;
        CPWAIT1();
        __syncthreads();                                   // (1) K/V visible

        // ---------- Phase A: S[16x16] 3-term hi/lo mma ----------
        float s[2][4];
        #pragma unroll
        for (int t = 0; t < 2; t++)
            #pragma unroll
            for (int i = 0; i < 4; i++) s[t][i] = 0.f;
        #pragma unroll
        for (int ks = 0; ks < 4; ks++) {
            uint32_t aqh[4], aql[4], bkh[4], bkl[4];
            ldsm4(aqh, frag128(SM_QH, rows0, ks));
            ldsm4(aql, frag128(SM_QL, rows0, ks));
            ldsm4(bkh, frag128(SM_KH(b), key0, ks));
            ldsm4(bkl, frag128(SM_KL(b), key0, ks));
            mma16816(s[0], aqh, bkh[0], bkh[2]);
            mma16816(s[1], aqh, bkh[1], bkh[3]);
            mma16816(s[0], aqh, bkl[0], bkl[2]);
            mma16816(s[1], aqh, bkl[1], bkl[3]);
            mma16816(s[0], aql, bkh[0], bkh[2]);
            mma16816(s[1], aql, bkh[1], bkh[3]);
        }

        // ---------- Phase B: publish per-(kg,row) partial max ----------
        float ma = fmaxf(fmaxf(s[0][0], s[0][1]), fmaxf(s[1][0], s[1][1]));
        float mb = fmaxf(fmaxf(s[0][2], s[0][3]), fmaxf(s[1][2], s[1][3]));
        ma = fmaxf(ma, __shfl_xor_sync(0xffffffffu, ma, 1));
        ma = fmaxf(ma, __shfl_xor_sync(0xffffffffu, ma, 2));
        mb = fmaxf(mb, __shfl_xor_sync(0xffffffffu, mb, 1));
        mb = fmaxf(mb, __shfl_xor_sync(0xffffffffu, mb, 2));
        if (lc == 0) {
            stats[IX_PMAX(kg, row_a)] = ma;
            stats[IX_PMAX(kg, row_b)] = mb;
        }
        __syncthreads();                                   // (2) partials visible

        // ---------- Phase CD: redundant max combine, owners publish corr ----------
        if (tid < 64) {
            float mo = stats[IX_MROW(cur, tid)], mn = mo;
            #pragma unroll
            for (int g = 0; g < 4; g++) mn = fmaxf(mn, stats[IX_PMAX(g, tid)]);
            corr_loc = __expf(mo - mn);
            stats[IX_MROW(nxt, tid)] = mn;
            stats[IX_CORR(tid)] = corr_loc;
        }
        {
            float mA = stats[IX_MROW(cur, row_a)];
            float mB = stats[IX_MROW(cur, row_b)];
            #pragma unroll
            for (int g = 0; g < 4; g++) {
                mA = fmaxf(mA, stats[IX_PMAX(g, row_a)]);
                mB = fmaxf(mB, stats[IX_PMAX(g, row_b)]);
            }
            float la = 0.f, lb = 0.f;
            #pragma unroll
            for (int t = 0; t < 2; t++) {
                float p0 = __expf(s[t][0] - mA);
                float p1 = __expf(s[t][1] - mA);
                float p2 = __expf(s[t][2] - mB);
                float p3 = __expf(s[t][3] - mB);
                la += p0 + p1;
                lb += p2 + p3;
                __half2 hA = __floats2half2_rn(p0, p1);
                __half2 hB = __floats2half2_rn(p2, p3);
                int ch = kg * 2 + t;
                *(uint32_t*)(smem + SM_P + row_a * 128 + ((ch ^ (row_a & 7)) * 16) + lc * 4) =
                    *(uint32_t*)&hA;
                *(uint32_t*)(smem + SM_P + row_b * 128 + ((ch ^ (row_b & 7)) * 16) + lc * 4) =
                    *(uint32_t*)&hB;
            }
            la += __shfl_xor_sync(0xffffffffu, la, 1);
            la += __shfl_xor_sync(0xffffffffu, la, 2);
            lb += __shfl_xor_sync(0xffffffffu, lb, 1);
            lb += __shfl_xor_sync(0xffffffffu, lb, 2);
            if (lc == 0) {
                stats[IX_PSUM(kg, row_a)] = la;
                stats[IX_PSUM(kg, row_b)] = lb;
            }
        }
        __syncthreads();                                   // (3) P + corr + psums visible

        // ---------- Phase E: l update, acc rescale, PV mma ----------
        if (tid < 64) {
            float ls = 0.f;
            #pragma unroll
            for (int g = 0; g < 4; g++) ls += stats[IX_PSUM(g, tid)];
            l_reg = l_reg * corr_loc + ls;
        }
        {
            float cr[4][2];
            bool allone = true;
            #pragma unroll
            for (int rt = 0; rt < 4; rt++) {
                cr[rt][0] = stats[IX_CORR(rt * 16 + lq)];
                cr[rt][1] = stats[IX_CORR(rt * 16 + lq + 8)];
                allone = allone && (cr[rt][0] == 1.0f) && (cr[rt][1] == 1.0f);
            }
            if (!__all_sync(0xffffffffu, allone)) {
                #pragma unroll
                for (int rt = 0; rt < 4; rt++)
                    #pragma unroll
                    for (int n = 0; n < 4; n++) {
                        o[rt][n][0] *= cr[rt][0]; o[rt][n][1] *= cr[rt][0];
                        o[rt][n][2] *= cr[rt][1]; o[rt][n][3] *= cr[rt][1];
                    }
            }
        }
        #pragma unroll
        for (int ks = 0; ks < 4; ks++) {
            uint32_t vf[2][4];
            ldsm4t(vf[0], fragV(b, ks * 16, chW + 0));
            ldsm4t(vf[1], fragV(b, ks * 16, chW + 16));
            #pragma unroll
            for (int rt = 0; rt < 4; rt++) {
                uint32_t ap[4];
                ldsm4(ap, frag128(SM_P, rt * 16, ks));
                mma16816(o[rt][0], ap, vf[0][0], vf[0][1]);
                mma16816(o[rt][1], ap, vf[0][2], vf[0][3]);
                mma16816(o[rt][2], ap, vf[1][0], vf[1][1]);
                mma16816(o[rt][3], ap, vf[1][2], vf[1][3]);
            }
        }
        __syncthreads();                                   // (4) V/K/P consumed

        if (it + 2 < ITERS) load_kv(SB, Kh, Kl, Vh, (it + 2) * BN, b, tid);
        CPCOMMIT();
    }

    // ---------- epilogue ----------
    if (tid < 64) stats[IX_CORR(tid)] = 1.0f / l_reg;
    __syncthreads();
    #pragma unroll
    for (int rt = 0; rt < 4; rt++) {
        int rA = rt * 16 + lq, rB = rA + 8;
        float ia = stats[IX_CORR(rA)];
        float ib = stats[IX_CORR(rB)];
        const size_t ra = (size_t)(qBase + rA) * CIN;
        const size_t rb = (size_t)(qBase + rB) * CIN;
        #pragma unroll
        for (int n = 0; n < 4; n++) {
            int c = chW + n * 8 + lc * 2;
            float2 r2 = *(const float2*)(resid + ra + c);
            *(float2*)(out + ra + c) =
                make_float2(fmaf(o[rt][n][0], ia, r2.x), fmaf(o[rt][n][1], ia, r2.y));
            float2 r3 = *(const float2*)(resid + rb + c);
            *(float2*)(out + rb + c) =
                make_float2(fmaf(o[rt][n][2], ib, r3.x), fmaf(o[rt][n][3], ib, r3.y));
        }
    }
}

extern "C" void kernel_launch(void* const* d_in, const int* in_sizes, int n_in,
                              void* d_out, int out_size) {
    const float* im1 = (const float*)d_in[0];
    const float* im2 = (const float*)d_in[1];
    const float* Wq  = (const float*)d_in[2];
    const float* Wk  = (const float*)d_in[3];
    const float* Wv  = (const float*)d_in[4];
    float* out = (float*)d_out;

    cudaFuncSetAttribute(attn_kernel, cudaFuncAttributeMaxDynamicSharedMemorySize, SM_TOTAL);

    dim3 pgrid(NTOK / 128, PCOLS / 64, 2);
    proj_kernel<<<pgrid, 256>>>(im1, im2, Wq, Wk, Wv);

    dim3 agrid(NTOK / BM, 2);
    attn_kernel<<<agrid, 512, SM_TOTAL>>>(im1, im2, out);
}

// round 11
// speedup vs baseline: 9.6491x; 1.0122x over previous
#include <cuda_runtime.h>
#include <cuda_fp16.h>
#include <cstdint>

#define NTOK 8192
#define CIN 512
#define DK 64
#define BM 64            // queries per CTA (attn)
#define BN 64            // keys per iteration
#define ITERS (NTOK / BN)
#define PCOLS 640

// ---------------- static scratch (fp16 operands) ----------------
__device__ __align__(16) __half g_qh[2][NTOK * DK];
__device__ __align__(16) __half g_ql[2][NTOK * DK];
__device__ __align__(16) __half g_kh[2][NTOK * DK];
__device__ __align__(16) __half g_kl[2][NTOK * DK];
__device__ __align__(16) __half g_vh[2][(size_t)NTOK * CIN];

// ---------------- PTX helpers (base ISA only) ----------------
__device__ __forceinline__ uint32_t smem_u32(const void* p) {
    uint32_t a;
    asm("{ .reg .u64 t; cvta.to.shared.u64 t, %1; cvt.u32.u64 %0, t; }" : "=r"(a) : "l"(p));
    return a;
}
__device__ __forceinline__ void mma16816(float* c, const uint32_t* a, uint32_t b0, uint32_t b1) {
    asm volatile(
        "mma.sync.aligned.m16n8k16.row.col.f32.f16.f16.f32 "
        "{%0,%1,%2,%3}, {%4,%5,%6,%7}, {%8,%9}, {%0,%1,%2,%3};"
        : "+f"(c[0]), "+f"(c[1]), "+f"(c[2]), "+f"(c[3])
        : "r"(a[0]), "r"(a[1]), "r"(a[2]), "r"(a[3]), "r"(b0), "r"(b1));
}
__device__ __forceinline__ void ldsm4(uint32_t* d, uint32_t addr) {
    asm volatile("ldmatrix.sync.aligned.m8n8.x4.shared.b16 {%0,%1,%2,%3}, [%4];"
                 : "=r"(d[0]), "=r"(d[1]), "=r"(d[2]), "=r"(d[3]) : "r"(addr));
}
__device__ __forceinline__ void ldsm4t(uint32_t* d, uint32_t addr) {
    asm volatile("ldmatrix.sync.aligned.m8n8.x4.trans.shared.b16 {%0,%1,%2,%3}, [%4];"
                 : "=r"(d[0]), "=r"(d[1]), "=r"(d[2]), "=r"(d[3]) : "r"(addr));
}
#define CP16(dst, src)  asm volatile("cp.async.cg.shared.global [%0], [%1], 16;" :: "r"(dst), "l"(src))
#define CPCOMMIT()      asm volatile("cp.async.commit_group;" ::: "memory")
#define CPWAIT0()       asm volatile("cp.async.wait_group 0;" ::: "memory")

// ---------------------------------------------------------------------------
// Kernel 1: HMMA QKV projection (unchanged from R10; ~108us).
// ---------------------------------------------------------------------------
__global__ __launch_bounds__(256, 2)
void proj_kernel(const float* __restrict__ im1, const float* __restrict__ im2,
                 const float* __restrict__ Wq, const float* __restrict__ Wk,
                 const float* __restrict__ Wv) {
    const int img = blockIdx.z;
    const float* __restrict__ A = img ? im2 : im1;
    const int rowBase = blockIdx.x * 128;
    const int colBase = blockIdx.y * 64;

    __shared__ __align__(16) __half Ah[128 * 32];
    __shared__ __align__(16) __half Al[128 * 32];
    __shared__ __align__(16) __half Wh[32 * 64];
    __shared__ __align__(16) __half Wl[32 * 64];

    const int tid = threadIdx.x, warp = tid >> 5, lane = tid & 31;
    const int wr = warp & 3, wc = warp >> 2;
    const int l7 = lane & 7, l8 = (lane >> 3) & 1, l16 = lane >> 4;
    const int lq = lane >> 2, lc = lane & 3;

    const uint32_t sAh = smem_u32(Ah), sAl = smem_u32(Al);
    const uint32_t sWh = smem_u32(Wh), sWl = smem_u32(Wl);

    float o[2][4][4] = {};
    float4 aR[4];
    float4 wR[2];

    auto loadA = [&](int kt) {
        #pragma unroll
        for (int i = 0; i < 4; i++) {
            int idx = tid + i * 256;
            int r = idx >> 3, c4 = idx & 7;
            aR[i] = *(const float4*)(A + (size_t)(rowBase + r) * CIN + kt * 32 + c4 * 4);
        }
    };
    auto loadW = [&](int kt) {
        #pragma unroll
        for (int i = 0; i < 2; i++) {
            int idx = tid + i * 256;
            int r = idx >> 4, c4 = idx & 15;
            int krow = kt * 32 + r;
            int c = colBase + c4 * 4;
            const float* src;
            if (c < 64)       src = Wq + krow * DK + c;
            else if (c < 128) src = Wk + krow * DK + (c - 64);
            else              src = Wv + krow * CIN + (c - 128);
            wR[i] = *(const float4*)src;
        }
    };

    loadA(0); loadW(0);

    for (int kt = 0; kt < 16; kt++) {
        #pragma unroll
        for (int i = 0; i < 4; i++) {
            int idx = tid + i * 256;
            int r = idx >> 3, c4 = idx & 7;
            uint32_t off = (uint32_t)(r * 64 + (((c4 >> 1) ^ (r & 3)) * 16) + (c4 & 1) * 8);
            float4 v = aR[i];
            __half h0 = __float2half_rn(v.x), h1 = __float2half_rn(v.y);
            __half h2 = __float2half_rn(v.z), h3 = __float2half_rn(v.w);
            __half2 H0 = __halves2half2(h0, h1), H1 = __halves2half2(h2, h3);
            __half2 L0 = __halves2half2(__float2half_rn(v.x - __half2float(h0)),
                                        __float2half_rn(v.y - __half2float(h1)));
            __half2 L1 = __halves2half2(__float2half_rn(v.z - __half2float(h2)),
                                        __float2half_rn(v.w - __half2float(h3)));
            *(uint2*)((char*)Ah + off) = make_uint2(*(uint32_t*)&H0, *(uint32_t*)&H1);
            *(uint2*)((char*)Al + off) = make_uint2(*(uint32_t*)&L0, *(uint32_t*)&L1);
        }
        #pragma unroll
        for (int i = 0; i < 2; i++) {
            int idx = tid + i * 256;
            int r = idx >> 4, c4 = idx & 15;
            uint32_t off = (uint32_t)(r * 128 + (((c4 >> 1) ^ (r & 7)) * 16) + (c4 & 1) * 8);
            float4 v = wR[i];
            __half h0 = __float2half_rn(v.x), h1 = __float2half_rn(v.y);
            __half h2 = __float2half_rn(v.z), h3 = __float2half_rn(v.w);
            __half2 H0 = __halves2half2(h0, h1), H1 = __halves2half2(h2, h3);
            __half2 L0 = __halves2half2(__float2half_rn(v.x - __half2float(h0)),
                                        __float2half_rn(v.y - __half2float(h1)));
            __half2 L1 = __halves2half2(__float2half_rn(v.z - __half2float(h2)),
                                        __float2half_rn(v.w - __half2float(h3)));
            *(uint2*)((char*)Wh + off) = make_uint2(*(uint32_t*)&H0, *(uint32_t*)&H1);
            *(uint2*)((char*)Wl + off) = make_uint2(*(uint32_t*)&L0, *(uint32_t*)&L1);
        }
        __syncthreads();

        if (kt + 1 < 16) { loadA(kt + 1); loadW(kt + 1); }

        #pragma unroll
        for (int ks = 0; ks < 2; ks++) {
            uint32_t wh[2][4], wl[2][4];
            #pragma unroll
            for (int nt = 0; nt < 2; nt++) {
                int rr = ks * 16 + l7 + l8 * 8;
                uint32_t chunk = (uint32_t)((wc * 4 + nt * 2 + l16) ^ (rr & 7));
                ldsm4t(wh[nt], sWh + rr * 128 + chunk * 16);
                ldsm4t(wl[nt], sWl + rr * 128 + chunk * 16);
            }
            #pragma unroll
            for (int rt = 0; rt < 2; rt++) {
                int ar = wr * 32 + rt * 16 + l7 + l8 * 8;
                uint32_t ach = (uint32_t)((ks * 2 + l16) ^ (ar & 3));
                uint32_t ah[4], al[4];
                ldsm4(ah, sAh + ar * 64 + ach * 16);
                ldsm4(al, sAl + ar * 64 + ach * 16);
                #pragma unroll
                for (int nt = 0; nt < 2; nt++) {
                    mma16816(o[rt][nt * 2 + 0], ah, wh[nt][0], wh[nt][1]);
                    mma16816(o[rt][nt * 2 + 1], ah, wh[nt][2], wh[nt][3]);
                    mma16816(o[rt][nt * 2 + 0], ah, wl[nt][0], wl[nt][1]);
                    mma16816(o[rt][nt * 2 + 1], ah, wl[nt][2], wl[nt][3]);
                    mma16816(o[rt][nt * 2 + 0], al, wh[nt][0], wh[nt][1]);
                    mma16816(o[rt][nt * 2 + 1], al, wh[nt][2], wh[nt][3]);
                }
            }
        }
        __syncthreads();
    }

    #pragma unroll
    for (int rt = 0; rt < 2; rt++) {
        #pragma unroll
        for (int n = 0; n < 4; n++) {
            int rowA = rowBase + wr * 32 + rt * 16 + lq;
            int rowB = rowA + 8;
            int cA = wc * 32 + n * 8 + lc * 2;
            float v0 = o[rt][n][0], v1 = o[rt][n][1];
            float v2 = o[rt][n][2], v3 = o[rt][n][3];
            if (colBase == 0) {
                __half h0 = __float2half_rn(v0), h1 = __float2half_rn(v1);
                __half h2 = __float2half_rn(v2), h3 = __float2half_rn(v3);
                *(__half2*)&g_qh[img][rowA * DK + cA] = __halves2half2(h0, h1);
                *(__half2*)&g_qh[img][rowB * DK + cA] = __halves2half2(h2, h3);
                *(__half2*)&g_ql[img][rowA * DK + cA] =
                    __halves2half2(__float2half_rn(v0 - __half2float(h0)),
                                   __float2half_rn(v1 - __half2float(h1)));
                *(__half2*)&g_ql[img][rowB * DK + cA] =
                    __halves2half2(__float2half_rn(v2 - __half2float(h2)),
                                   __float2half_rn(v3 - __half2float(h3)));
            } else if (colBase == 64) {
                __half h0 = __float2half_rn(v0), h1 = __float2half_rn(v1);
                __half h2 = __float2half_rn(v2), h3 = __float2half_rn(v3);
                *(__half2*)&g_kh[img][rowA * DK + cA] = __halves2half2(h0, h1);
                *(__half2*)&g_kh[img][rowB * DK + cA] = __halves2half2(h2, h3);
                *(__half2*)&g_kl[img][rowA * DK + cA] =
                    __halves2half2(__float2half_rn(v0 - __half2float(h0)),
                                   __float2half_rn(v1 - __half2float(h1)));
                *(__half2*)&g_kl[img][rowB * DK + cA] =
                    __halves2half2(__float2half_rn(v2 - __half2float(h2)),
                                   __float2half_rn(v3 - __half2float(h3)));
            } else {
                int cv = colBase - 128 + cA;
                *(__half2*)&g_vh[img][(size_t)rowA * CIN + cv] =
                    __halves2half2(__float2half_rn(v0), __float2half_rn(v1));
                *(__half2*)&g_vh[img][(size_t)rowB * CIN + cv] =
                    __halves2half2(__float2half_rn(v2), __float2half_rn(v3));
            }
        }
    }
}

// ---------------- attn smem layout ----------------
#define IX_MROW(cur, row) ((cur) * 64 + (row))
#define IX_CORR(row)      (128 + (row))
#define IX_PMAX(g, row)   (192 + (g) * 64 + (row))
#define IX_PSUM(g, row)   (448 + (g) * 64 + (row))
#define SM_QH    3072
#define SM_QL    (SM_QH + 8192)
#define SM_KH(b) (19456 + (b) * 16384)
#define SM_KL(b) (27648 + (b) * 16384)
#define SM_V(b)  (52224 + (b) * 65536)
#define SM_P(b)  (183296 + (b) * 16384)
#define SM_TOTAL 216064

__device__ __forceinline__ void load_kv(uint32_t SB, const __half* Kh, const __half* Kl,
                                        const __half* Vh, int kb, int buf, int tid) {
    int r = tid >> 3, c = tid & 7;
    uint32_t sw = (uint32_t)((c ^ (r & 7)) * 16);
    CP16(SB + SM_KH(buf) + r * 128 + sw, Kh + (size_t)(kb + r) * DK + c * 8);
    CP16(SB + SM_KL(buf) + r * 128 + sw, Kl + (size_t)(kb + r) * DK + c * 8);
    #pragma unroll
    for (int i = 0; i < 8; i++) {
        int idx = tid + i * 512;
        int vr = idx >> 6, vc = idx & 63;
        CP16(SB + SM_V(buf) + vr * 1024 + (uint32_t)((vc ^ (vr & 7)) * 16),
             Vh + (size_t)(kb + vr) * CIN + vc * 8);
    }
}

// ---------------------------------------------------------------------------
// Kernel 2: HMMA flash attention, PV deferred one iteration (tensor overlap).
// grid (128 qblocks, 2 sides), 512 threads. 2 barriers/iter.
// ---------------------------------------------------------------------------
__global__ __launch_bounds__(512, 1)
void attn_kernel(const float* __restrict__ im1, const float* __restrict__ im2,
                 float* __restrict__ out_all) {
    extern __shared__ char smem[];
    const uint32_t SB = smem_u32(smem);
    float* const stats = (float*)smem;

    const int tid  = threadIdx.x;
    const int warp = tid >> 5;
    const int lane = tid & 31;
    const int side  = blockIdx.y;
    const int qBase = blockIdx.x * BM;

    const __half* __restrict__ Qh = g_qh[side ^ 1];
    const __half* __restrict__ Ql = g_ql[side ^ 1];
    const __half* __restrict__ Kh = g_kh[side];
    const __half* __restrict__ Kl = g_kl[side];
    const __half* __restrict__ Vh = g_vh[side];
    const float* __restrict__ resid = side ? im2 : im1;
    float* __restrict__ out = out_all + (size_t)side * NTOK * CIN;

    const int rg = warp & 3;
    const int kg = warp >> 2;
    const int rows0 = rg * 16;
    const int key0  = kg * 16;
    const int chW   = warp * 32;

    const int l7  = lane & 7;
    const int l8  = (lane >> 3) & 1;
    const int l16 = lane >> 4;
    const int lq  = lane >> 2;
    const int lc  = lane & 3;
    const int row_a = rows0 + lq;
    const int row_b = row_a + 8;

    auto frag128 = [&](uint32_t base, int row0, int ks) -> uint32_t {
        int r  = row0 + l7 + l8 * 8;
        int ch = ks * 2 + l16;
        return SB + base + r * 128 + (uint32_t)(((ch ^ (r & 7)) & 7) * 16);
    };
    auto fragV = [&](int buf, int k0, int n0) -> uint32_t {
        int r  = k0 + l7 + l8 * 8;
        int ch = (n0 >> 3) + l16;
        return SB + SM_V(buf) + r * 1024 + (uint32_t)((ch ^ (r & 7)) * 16);
    };

    // ---- prologue: Q + K/V(0), single group, full visibility ----
    if (tid < 64) stats[IX_MROW(0, tid)] = -1e30f;
    {
        int r = tid >> 3, c = tid & 7;
        uint32_t sw = (uint32_t)((c ^ (r & 7)) * 16);
        CP16(SB + SM_QH + r * 128 + sw, Qh + (size_t)(qBase + r) * DK + c * 8);
        CP16(SB + SM_QL + r * 128 + sw, Ql + (size_t)(qBase + r) * DK + c * 8);
        load_kv(SB, Kh, Kl, Vh, 0, 0, tid);
        CPCOMMIT();
    }
    CPWAIT0();
    __syncthreads();

    float o[4][4][4];
    #pragma unroll
    for (int rt = 0; rt < 4; rt++)
        #pragma unroll
        for (int n = 0; n < 4; n++)
            #pragma unroll
            for (int i = 0; i < 4; i++) o[rt][n][i] = 0.f;
    float l_reg = 0.f, corr_prev = 0.f;   // owner state (tid < 64)

    for (int it = 0; it < ITERS; it++) {
        const int b   = it & 1;
        const int bp  = b ^ 1;
        const int cur = it & 1, nxt = cur ^ 1;

        // ---------- Phase 1: QK(it) ----------
        float s[2][4];
        #pragma unroll
        for (int t = 0; t < 2; t++)
            #pragma unroll
            for (int i = 0; i < 4; i++) s[t][i] = 0.f;
        #pragma unroll
        for (int ks = 0; ks < 4; ks++) {
            uint32_t aqh[4], aql[4], bkh[4], bkl[4];
            ldsm4(aqh, frag128(SM_QH, rows0, ks));
            ldsm4(aql, frag128(SM_QL, rows0, ks));
            ldsm4(bkh, frag128(SM_KH(b), key0, ks));
            ldsm4(bkl, frag128(SM_KL(b), key0, ks));
            mma16816(s[0], aqh, bkh[0], bkh[2]);
            mma16816(s[1], aqh, bkh[1], bkh[3]);
            mma16816(s[0], aqh, bkl[0], bkl[2]);
            mma16816(s[1], aqh, bkl[1], bkl[3]);
            mma16816(s[0], aql, bkh[0], bkh[2]);
            mma16816(s[1], aql, bkh[1], bkh[3]);
        }

        // ---------- Phase 2: deferred PV(it-1) (overlaps later softmax) ----------
        if (it > 0) {
            if (tid < 64) {
                float ls = 0.f;
                #pragma unroll
                for (int g = 0; g < 4; g++) ls += stats[IX_PSUM(g, tid)];
                l_reg = l_reg * corr_prev + ls;
            }
            {
                float cr[4][2];
                bool allone = true;
                #pragma unroll
                for (int rt = 0; rt < 4; rt++) {
                    cr[rt][0] = stats[IX_CORR(rt * 16 + lq)];
                    cr[rt][1] = stats[IX_CORR(rt * 16 + lq + 8)];
                    allone = allone && (cr[rt][0] == 1.0f) && (cr[rt][1] == 1.0f);
                }
                if (!__all_sync(0xffffffffu, allone)) {
                    #pragma unroll
                    for (int rt = 0; rt < 4; rt++)
                        #pragma unroll
                        for (int n = 0; n < 4; n++) {
                            o[rt][n][0] *= cr[rt][0]; o[rt][n][1] *= cr[rt][0];
                            o[rt][n][2] *= cr[rt][1]; o[rt][n][3] *= cr[rt][1];
                        }
                }
            }
            #pragma unroll
            for (int ks = 0; ks < 4; ks++) {
                uint32_t vf[2][4];
                ldsm4t(vf[0], fragV(bp, ks * 16, chW + 0));
                ldsm4t(vf[1], fragV(bp, ks * 16, chW + 16));
                #pragma unroll
                for (int rt = 0; rt < 4; rt++) {
                    uint32_t ap[4];
                    ldsm4(ap, frag128(SM_P(bp), rt * 16, ks));
                    mma16816(o[rt][0], ap, vf[0][0], vf[0][1]);
                    mma16816(o[rt][1], ap, vf[0][2], vf[0][3]);
                    mma16816(o[rt][2], ap, vf[1][0], vf[1][1]);
                    mma16816(o[rt][3], ap, vf[1][2], vf[1][3]);
                }
            }
        }

        // ---------- Phase 3a: publish partial maxima ----------
        float ma = fmaxf(fmaxf(s[0][0], s[0][1]), fmaxf(s[1][0], s[1][1]));
        float mb = fmaxf(fmaxf(s[0][2], s[0][3]), fmaxf(s[1][2], s[1][3]));
        ma = fmaxf(ma, __shfl_xor_sync(0xffffffffu, ma, 1));
        ma = fmaxf(ma, __shfl_xor_sync(0xffffffffu, ma, 2));
        mb = fmaxf(mb, __shfl_xor_sync(0xffffffffu, mb, 1));
        mb = fmaxf(mb, __shfl_xor_sync(0xffffffffu, mb, 2));
        if (lc == 0) {
            stats[IX_PMAX(kg, row_a)] = ma;
            stats[IX_PMAX(kg, row_b)] = mb;
        }
        __syncthreads();                                   // barrier #1

        // ---------- Phase 3b: prefetch K/V(it+1) into buf bp (just freed) ----------
        if (it + 1 < ITERS) load_kv(SB, Kh, Kl, Vh, (it + 1) * BN, bp, tid);
        CPCOMMIT();

        // ---------- Phase 3c: combine, exp, write P(it), psums ----------
        if (tid < 64) {
            float mo = stats[IX_MROW(cur, tid)], mn = mo;
            #pragma unroll
            for (int g = 0; g < 4; g++) mn = fmaxf(mn, stats[IX_PMAX(g, tid)]);
            corr_prev = __expf(mo - mn);
            stats[IX_MROW(nxt, tid)] = mn;
            stats[IX_CORR(tid)] = corr_prev;
        }
        {
            float mA = stats[IX_MROW(cur, row_a)];
            float mB = stats[IX_MROW(cur, row_b)];
            #pragma unroll
            for (int g = 0; g < 4; g++) {
                mA = fmaxf(mA, stats[IX_PMAX(g, row_a)]);
                mB = fmaxf(mB, stats[IX_PMAX(g, row_b)]);
            }
            float la = 0.f, lb = 0.f;
            #pragma unroll
            for (int t = 0; t < 2; t++) {
                float p0 = __expf(s[t][0] - mA);
                float p1 = __expf(s[t][1] - mA);
                float p2 = __expf(s[t][2] - mB);
                float p3 = __expf(s[t][3] - mB);
                la += p0 + p1;
                lb += p2 + p3;
                __half2 hA = __floats2half2_rn(p0, p1);
                __half2 hB = __floats2half2_rn(p2, p3);
                int ch = kg * 2 + t;
                *(uint32_t*)(smem + SM_P(b) + row_a * 128 + ((ch ^ (row_a & 7)) * 16) + lc * 4) =
                    *(uint32_t*)&hA;
                *(uint32_t*)(smem + SM_P(b) + row_b * 128 + ((ch ^ (row_b & 7)) * 16) + lc * 4) =
                    *(uint32_t*)&hB;
            }
            la += __shfl_xor_sync(0xffffffffu, la, 1);
            la += __shfl_xor_sync(0xffffffffu, la, 2);
            lb += __shfl_xor_sync(0xffffffffu, lb, 1);
            lb += __shfl_xor_sync(0xffffffffu, lb, 2);
            if (lc == 0) {
                stats[IX_PSUM(kg, row_a)] = la;
                stats[IX_PSUM(kg, row_b)] = lb;
            }
        }
        CPWAIT0();
        __syncthreads();                                   // barrier #2
    }

    // ---------- epilogue: final PV(ITERS-1) ----------
    {
        const int bl = (ITERS - 1) & 1;
        if (tid < 64) {
            float ls = 0.f;
            #pragma unroll
            for (int g = 0; g < 4; g++) ls += stats[IX_PSUM(g, tid)];
            l_reg = l_reg * corr_prev + ls;
        }
        {
            float cr[4][2];
            bool allone = true;
            #pragma unroll
            for (int rt = 0; rt < 4; rt++) {
                cr[rt][0] = stats[IX_CORR(rt * 16 + lq)];
                cr[rt][1] = stats[IX_CORR(rt * 16 + lq + 8)];
                allone = allone && (cr[rt][0] == 1.0f) && (cr[rt][1] == 1.0f);
            }
            if (!__all_sync(0xffffffffu, allone)) {
                #pragma unroll
                for (int rt = 0; rt < 4; rt++)
                    #pragma unroll
                    for (int n = 0; n < 4; n++) {
                        o[rt][n][0] *= cr[rt][0]; o[rt][n][1] *= cr[rt][0];
                        o[rt][n][2] *= cr[rt][1]; o[rt][n][3] *= cr[rt][1];
                    }
            }
        }
        #pragma unroll
        for (int ks = 0; ks < 4; ks++) {
            uint32_t vf[2][4];
            ldsm4t(vf[0], fragV(bl, ks * 16, chW + 0));
            ldsm4t(vf[1], fragV(bl, ks * 16, chW + 16));
            #pragma unroll
            for (int rt = 0; rt < 4; rt++) {
                uint32_t ap[4];
                ldsm4(ap, frag128(SM_P(bl), rt * 16, ks));
                mma16816(o[rt][0], ap, vf[0][0], vf[0][1]);
                mma16816(o[rt][1], ap, vf[0][2], vf[0][3]);
                mma16816(o[rt][2], ap, vf[1][0], vf[1][1]);
                mma16816(o[rt][3], ap, vf[1][2], vf[1][3]);
            }
        }
    }

    __syncthreads();
    if (tid < 64) stats[IX_CORR(tid)] = 1.0f / l_reg;
    __syncthreads();
    #pragma unroll
    for (int rt = 0; rt < 4; rt++) {
        int rA = rt * 16 + lq, rB = rA + 8;
        float ia = stats[IX_CORR(rA)];
        float ib = stats[IX_CORR(rB)];
        const size_t ra = (size_t)(qBase + rA) * CIN;
        const size_t rb = (size_t)(qBase + rB) * CIN;
        #pragma unroll
        for (int n = 0; n < 4; n++) {
            int c = chW + n * 8 + lc * 2;
            float2 r2 = *(const float2*)(resid + ra + c);
            *(float2*)(out + ra + c) =
                make_float2(fmaf(o[rt][n][0], ia, r2.x), fmaf(o[rt][n][1], ia, r2.y));
            float2 r3 = *(const float2*)(resid + rb + c);
            *(float2*)(out + rb + c) =
                make_float2(fmaf(o[rt][n][2], ib, r3.x), fmaf(o[rt][n][3], ib, r3.y));
        }
    }
}

extern "C" void kernel_launch(void* const* d_in, const int* in_sizes, int n_in,
                              void* d_out, int out_size) {
    const float* im1 = (const float*)d_in[0];
    const float* im2 = (const float*)d_in[1];
    const float* Wq  = (const float*)d_in[2];
    const float* Wk  = (const float*)d_in[3];
    const float* Wv  = (const float*)d_in[4];
    float* out = (float*)d_out;

    cudaFuncSetAttribute(attn_kernel, cudaFuncAttributeMaxDynamicSharedMemorySize, SM_TOTAL);

    dim3 pgrid(NTOK / 128, PCOLS / 64, 2);
    proj_kernel<<<pgrid, 256>>>(im1, im2, Wq, Wk, Wv);

    dim3 agrid(NTOK / BM, 2);
    attn_kernel<<<agrid, 512, SM_TOTAL>>>(im1, im2, out);
}